// round 1
// baseline (speedup 1.0000x reference)
#include <cuda_runtime.h>
#include <math.h>

// Problem constants
#define Bsz   8
#define Ssz   2048
#define Hsz   8
#define IDsz  256
#define ODsz  256
#define Mrows (Bsz*Ssz*Hsz)    // 131072 rows (b,s,h)
#define Ktot  512              // 2*ID = ID+OD
#define N1    768              // 3*OD
#define BSN   (Bsz*Ssz)        // 16384 (b,s) pairs
#define SSTRIDE 2048           // H*ID floats between consecutive s

// Scratch (device globals: allocation-free per harness rules)
__device__ float g_csum[(size_t)Mrows*IDsz];   // 134 MB
__device__ float g_g  [(size_t)Mrows*N1];      // 402 MB  (raw gates)
__device__ float g_f  [(size_t)Mrows*ODsz];    // 134 MB  (forget gate)
__device__ float g_cell[(size_t)Mrows*ODsz];   // 134 MB  (igh, then cell in-place)
__device__ float g_mean[BSN];
__device__ float g_rstd[BSN];

__device__ __forceinline__ float sigmoidf_(float x) {
    return 1.0f / (1.0f + __expf(-x));
}

// ---------------------------------------------------------------------------
// Kernel 1: cumsum over S per (b,h,id). Block = 32 id-lanes x 16 s-chunks.
// Coalesced: warp lanes span 32 consecutive id (128B).
// ---------------------------------------------------------------------------
__global__ void cumsum_kernel(const float* __restrict__ x) {
    int lane = threadIdx.x;            // id within 32-tile
    int r    = threadIdx.y;            // s-chunk index (0..15)
    int idt  = blockIdx.x & 7;
    int h    = (blockIdx.x >> 3) & 7;
    int b    = blockIdx.x >> 6;
    int id   = idt * 32 + lane;
    size_t base = (size_t)b * Ssz * SSTRIDE + (size_t)h * IDsz + id;
    const int CH = Ssz / 16;           // 128 s per thread

    size_t p = base + (size_t)(r * CH) * SSTRIDE;
    float sum = 0.f;
    for (int i = 0; i < CH; i++) { sum += x[p]; p += SSTRIDE; }

    __shared__ float cs[16][32];
    cs[r][lane] = sum;
    __syncthreads();
    if (r == 0) {
        float a = 0.f;
        #pragma unroll
        for (int k2 = 0; k2 < 16; k2++) { float v = cs[k2][lane]; cs[k2][lane] = a; a += v; }
    }
    __syncthreads();

    float run = cs[r][lane];
    p = base + (size_t)(r * CH) * SSTRIDE;
    for (int i = 0; i < CH; i++) { run += x[p]; g_csum[p] = run; p += SSTRIDE; }
}

// ---------------------------------------------------------------------------
// Kernel 2: LayerNorm stats per (b,s) over the 2048 contiguous csum floats.
// ---------------------------------------------------------------------------
__global__ void stats_kernel() {
    int bs = blockIdx.x;
    const float4* p = (const float4*)(g_csum + (size_t)bs * 2048);
    float s = 0.f, ss = 0.f;
    for (int i = threadIdx.x; i < 512; i += 256) {
        float4 v = p[i];
        s  += v.x + v.y + v.z + v.w;
        ss += v.x*v.x + v.y*v.y + v.z*v.z + v.w*v.w;
    }
    #pragma unroll
    for (int o = 16; o; o >>= 1) {
        s  += __shfl_down_sync(0xffffffffu, s,  o);
        ss += __shfl_down_sync(0xffffffffu, ss, o);
    }
    __shared__ float ws[8], wss[8];
    int wid = threadIdx.x >> 5, lane = threadIdx.x & 31;
    if (lane == 0) { ws[wid] = s; wss[wid] = ss; }
    __syncthreads();
    if (threadIdx.x == 0) {
        float S1 = 0.f, S2 = 0.f;
        #pragma unroll
        for (int i = 0; i < 8; i++) { S1 += ws[i]; S2 += wss[i]; }
        float mean = S1 * (1.f / 2048.f);
        float var  = S2 * (1.f / 2048.f) - mean * mean;
        g_mean[bs] = mean;
        g_rstd[bs] = rsqrtf(var + 1e-6f);
    }
}

// ---------------------------------------------------------------------------
// SGEMM: 128x128 block tile, BK=16, 256 threads, 8x8 microtile.
// MODE 1: A = [heads | LN(csum)]  (LN fused into load), out -> g_g (+bias)
// MODE 2: A = [heads | cell],     epilogue out = sigmoid(acc+b_og)*cell
// K=512, N in {768,256}, M=131072 -> all tiles exact, no bounds checks.
// ---------------------------------------------------------------------------
template<int MODE>
__global__ __launch_bounds__(256, 2)
void gemm_kernel(const float* __restrict__ heads,
                 const float* __restrict__ W,
                 const float* __restrict__ bias,
                 const float* __restrict__ lnw,
                 const float* __restrict__ lnb,
                 float* __restrict__ out)
{
    __shared__ float As[16][128];
    __shared__ float Bs[16][128];
    int t  = threadIdx.x;
    int tx = t & 15, ty = t >> 4;
    int n0 = blockIdx.x * 128;
    int m0 = blockIdx.y * 128;

    float acc[8][8];
    #pragma unroll
    for (int i = 0; i < 8; i++)
        #pragma unroll
        for (int j = 0; j < 8; j++) acc[i][j] = 0.f;

    for (int k0 = 0; k0 < Ktot; k0 += 16) {
        // ---- load A tile (128 rows x 16 k), fused second-half transform ----
        #pragma unroll
        for (int qq = 0; qq < 2; qq++) {
            int q   = t + qq * 256;
            int row = q >> 2;
            int kq  = (q & 3) << 2;
            int k   = k0 + kq;
            int m   = m0 + row;
            float4 v;
            if (k < 256) {
                v = *(const float4*)(heads + (size_t)m * 256 + k);
            } else if (MODE == 1) {
                int j = k - 256;
                v = *(const float4*)(g_csum + (size_t)m * 256 + j);
                int bs = m >> 3, h = m & 7;
                float mu = g_mean[bs], rs = g_rstd[bs];
                float4 w  = *(const float4*)(lnw + h * 256 + j);
                float4 bb = *(const float4*)(lnb + h * 256 + j);
                v.x = (v.x - mu) * rs * w.x + bb.x;
                v.y = (v.y - mu) * rs * w.y + bb.y;
                v.z = (v.z - mu) * rs * w.z + bb.z;
                v.w = (v.w - mu) * rs * w.w + bb.w;
            } else {
                v = *(const float4*)(g_cell + (size_t)m * 256 + (k - 256));
            }
            As[kq + 0][row] = v.x; As[kq + 1][row] = v.y;
            As[kq + 2][row] = v.z; As[kq + 3][row] = v.w;
        }
        // ---- load B tile (128 o x 16 k), W is row-major [o][k], stride 512 ----
        #pragma unroll
        for (int qq = 0; qq < 2; qq++) {
            int q  = t + qq * 256;
            int o  = q >> 2;
            int kq = (q & 3) << 2;
            float4 v = *(const float4*)(W + (size_t)(n0 + o) * Ktot + k0 + kq);
            Bs[kq + 0][o] = v.x; Bs[kq + 1][o] = v.y;
            Bs[kq + 2][o] = v.z; Bs[kq + 3][o] = v.w;
        }
        __syncthreads();

        #pragma unroll
        for (int kk = 0; kk < 16; kk++) {
            float a[8], bb[8];
            *(float4*)(a)     = *(const float4*)&As[kk][ty * 8];
            *(float4*)(a + 4) = *(const float4*)&As[kk][ty * 8 + 4];
            *(float4*)(bb)    = *(const float4*)&Bs[kk][tx * 8];
            *(float4*)(bb + 4)= *(const float4*)&Bs[kk][tx * 8 + 4];
            #pragma unroll
            for (int i = 0; i < 8; i++)
                #pragma unroll
                for (int j = 0; j < 8; j++)
                    acc[i][j] = fmaf(a[i], bb[j], acc[i][j]);
        }
        __syncthreads();
    }

    int o0 = n0 + tx * 8;
    float4 b0 = *(const float4*)(bias + o0);
    float4 b1 = *(const float4*)(bias + o0 + 4);
    if (MODE == 1) {
        #pragma unroll
        for (int i = 0; i < 8; i++) {
            int m = m0 + ty * 8 + i;
            float4 v0 = make_float4(acc[i][0] + b0.x, acc[i][1] + b0.y,
                                    acc[i][2] + b0.z, acc[i][3] + b0.w);
            float4 v1 = make_float4(acc[i][4] + b1.x, acc[i][5] + b1.y,
                                    acc[i][6] + b1.z, acc[i][7] + b1.w);
            *(float4*)(g_g + (size_t)m * N1 + o0)     = v0;
            *(float4*)(g_g + (size_t)m * N1 + o0 + 4) = v1;
        }
    } else {
        #pragma unroll
        for (int i = 0; i < 8; i++) {
            int m = m0 + ty * 8 + i;
            float4 c0 = *(const float4*)(g_cell + (size_t)m * 256 + o0);
            float4 c1 = *(const float4*)(g_cell + (size_t)m * 256 + o0 + 4);
            float4 v0, v1;
            v0.x = sigmoidf_(acc[i][0] + b0.x) * c0.x;
            v0.y = sigmoidf_(acc[i][1] + b0.y) * c0.y;
            v0.z = sigmoidf_(acc[i][2] + b0.z) * c0.z;
            v0.w = sigmoidf_(acc[i][3] + b0.w) * c0.w;
            v1.x = sigmoidf_(acc[i][4] + b1.x) * c1.x;
            v1.y = sigmoidf_(acc[i][5] + b1.y) * c1.y;
            v1.z = sigmoidf_(acc[i][6] + b1.z) * c1.z;
            v1.w = sigmoidf_(acc[i][7] + b1.w) * c1.w;
            *(float4*)(out + (size_t)m * 256 + o0)     = v0;
            *(float4*)(out + (size_t)m * 256 + o0 + 4) = v1;
        }
    }
}

// ---------------------------------------------------------------------------
// Kernel 4: gate activations. g -> f = sigmoid(g1); igh = sigmoid(g0)*relu(g2)
// ---------------------------------------------------------------------------
__global__ void act_kernel() {
    unsigned idx = blockIdx.x * blockDim.x + threadIdx.x;  // float4 index, < 8388608
    int m = idx >> 6;
    int q = (idx & 63) << 2;
    const float* gp = g_g + (size_t)m * N1 + q;
    float4 g0 = *(const float4*)(gp);
    float4 g1 = *(const float4*)(gp + 256);
    float4 g2 = *(const float4*)(gp + 512);
    float4 f, ig;
    f.x = sigmoidf_(g1.x); f.y = sigmoidf_(g1.y);
    f.z = sigmoidf_(g1.z); f.w = sigmoidf_(g1.w);
    ig.x = sigmoidf_(g0.x) * fmaxf(g2.x, 0.f);
    ig.y = sigmoidf_(g0.y) * fmaxf(g2.y, 0.f);
    ig.z = sigmoidf_(g0.z) * fmaxf(g2.z, 0.f);
    ig.w = sigmoidf_(g0.w) * fmaxf(g2.w, 0.f);
    *(float4*)(g_f   + (size_t)m * 256 + q) = f;
    *(float4*)(g_cell + (size_t)m * 256 + q) = ig;
}

// ---------------------------------------------------------------------------
// Kernel 5: affine scan c <- f*c + igh over S. Associative blocked scan,
// same structure/coalescing as cumsum. Writes cell in-place over igh.
// ---------------------------------------------------------------------------
__global__ void scan_kernel(const float* __restrict__ init_cx) {
    int lane = threadIdx.x;
    int r    = threadIdx.y;
    int idt  = blockIdx.x & 7;
    int h    = (blockIdx.x >> 3) & 7;
    int b    = blockIdx.x >> 6;
    int od   = idt * 32 + lane;
    size_t base = (size_t)b * Ssz * SSTRIDE + (size_t)h * ODsz + od;
    const int CH = Ssz / 16;

    // phase 1: per-chunk affine transform (F, I):  c_out = F*c_in + I
    size_t p = base + (size_t)(r * CH) * SSTRIDE;
    float F = 1.f, I = 0.f;
    for (int i = 0; i < CH; i++) {
        float f = g_f[p], ig = g_cell[p];
        I = fmaf(f, I, ig);
        F *= f;
        p += SSTRIDE;
    }
    __shared__ float sF[16][32], sI[16][32];
    sF[r][lane] = F; sI[r][lane] = I;
    __syncthreads();
    // phase 2: prefix-compose across chunks, seeded by init_cx
    if (r == 0) {
        float c = init_cx[h * 256 + od];
        #pragma unroll
        for (int k2 = 0; k2 < 16; k2++) {
            float nf = sF[k2][lane], ni = sI[k2][lane];
            sI[k2][lane] = c;               // c entering chunk k2
            c = fmaf(nf, c, ni);
        }
    }
    __syncthreads();
    // phase 3: replay with correct incoming state, emit cell
    float c = sI[r][lane];
    p = base + (size_t)(r * CH) * SSTRIDE;
    for (int i = 0; i < CH; i++) {
        float f = g_f[p], ig = g_cell[p];
        c = fmaf(f, c, ig);
        g_cell[p] = c;
        p += SSTRIDE;
    }
}

// ---------------------------------------------------------------------------
extern "C" void kernel_launch(void* const* d_in, const int* in_sizes, int n_in,
                              void* d_out, int out_size)
{
    const float* heads   = (const float*)d_in[0];
    const float* W_hid   = (const float*)d_in[1];
    const float* b_hid   = (const float*)d_in[2];
    const float* W_og    = (const float*)d_in[3];
    const float* b_og    = (const float*)d_in[4];
    const float* ln_w    = (const float*)d_in[5];
    const float* ln_b    = (const float*)d_in[6];
    const float* init_cx = (const float*)d_in[7];
    float* out = (float*)d_out;

    cumsum_kernel<<<512, dim3(32, 16)>>>(heads);
    stats_kernel<<<BSN, 256>>>();
    gemm_kernel<1><<<dim3(N1 / 128, Mrows / 128), 256>>>(heads, W_hid, b_hid, ln_w, ln_b, nullptr);
    act_kernel<<<(Mrows * ODsz / 4) / 256, 256>>>();
    scan_kernel<<<512, dim3(32, 16)>>>(init_cx);
    gemm_kernel<2><<<dim3(256 / 128, Mrows / 128), 256>>>(heads, W_og, b_og, nullptr, nullptr, out);
}

// round 2
// speedup vs baseline: 1.0699x; 1.0699x over previous
#include <cuda_runtime.h>
#include <math.h>

// Problem constants
#define Bsz   8
#define Ssz   2048
#define Hsz   8
#define IDsz  256
#define ODsz  256
#define Mrows (Bsz*Ssz*Hsz)    // 131072 rows (b,s,h)
#define Ktot  512              // 2*ID = ID+OD
#define BSN   (Bsz*Ssz)        // 16384 (b,s) pairs
#define SSTRIDE 2048           // H*ID floats between consecutive s

// Scratch (device globals: allocation-free per harness rules)
__device__ float g_csum[(size_t)Mrows*IDsz];   // 134 MB
__device__ float g_f  [(size_t)Mrows*ODsz];    // 134 MB  (forget gate)
__device__ float g_cell[(size_t)Mrows*ODsz];   // 134 MB  (igh, then cell in-place)
__device__ float g_mean[BSN];
__device__ float g_rstd[BSN];

__device__ __forceinline__ float sigmoidf_(float x) {
    return 1.0f / (1.0f + __expf(-x));
}

// smem column swizzle: for k-row kk, column c stored at c ^ ((kk&12)<<1).
// Makes transpose STS.32 conflict-free (32 lanes hit 32 banks) and keeps
// float4 operand LDS aligned (xor of multiples of 8 floats).
__device__ __forceinline__ int swz(int kk) { return (kk & 12) << 1; }

// ---------------------------------------------------------------------------
// Kernel 1: cumsum over S per (b,h,id). Block = 32 id-lanes x 16 s-chunks.
// ---------------------------------------------------------------------------
__global__ void cumsum_kernel(const float* __restrict__ x) {
    int lane = threadIdx.x;
    int r    = threadIdx.y;
    int idt  = blockIdx.x & 7;
    int h    = (blockIdx.x >> 3) & 7;
    int b    = blockIdx.x >> 6;
    int id   = idt * 32 + lane;
    size_t base = (size_t)b * Ssz * SSTRIDE + (size_t)h * IDsz + id;
    const int CH = Ssz / 16;

    size_t p = base + (size_t)(r * CH) * SSTRIDE;
    float sum = 0.f;
    for (int i = 0; i < CH; i++) { sum += x[p]; p += SSTRIDE; }

    __shared__ float cs[16][32];
    cs[r][lane] = sum;
    __syncthreads();
    if (r == 0) {
        float a = 0.f;
        #pragma unroll
        for (int k2 = 0; k2 < 16; k2++) { float v = cs[k2][lane]; cs[k2][lane] = a; a += v; }
    }
    __syncthreads();

    float run = cs[r][lane];
    p = base + (size_t)(r * CH) * SSTRIDE;
    for (int i = 0; i < CH; i++) { run += x[p]; g_csum[p] = run; p += SSTRIDE; }
}

// ---------------------------------------------------------------------------
// Kernel 2: LayerNorm stats per (b,s) over 2048 contiguous csum floats.
// ---------------------------------------------------------------------------
__global__ void stats_kernel() {
    int bs = blockIdx.x;
    const float4* p = (const float4*)(g_csum + (size_t)bs * 2048);
    float s = 0.f, ss = 0.f;
    for (int i = threadIdx.x; i < 512; i += 256) {
        float4 v = p[i];
        s  += v.x + v.y + v.z + v.w;
        ss += v.x*v.x + v.y*v.y + v.z*v.z + v.w*v.w;
    }
    #pragma unroll
    for (int o = 16; o; o >>= 1) {
        s  += __shfl_down_sync(0xffffffffu, s,  o);
        ss += __shfl_down_sync(0xffffffffu, ss, o);
    }
    __shared__ float ws[8], wss[8];
    int wid = threadIdx.x >> 5, lane = threadIdx.x & 31;
    if (lane == 0) { ws[wid] = s; wss[wid] = ss; }
    __syncthreads();
    if (threadIdx.x == 0) {
        float S1 = 0.f, S2 = 0.f;
        #pragma unroll
        for (int i = 0; i < 8; i++) { S1 += ws[i]; S2 += wss[i]; }
        float mean = S1 * (1.f / 2048.f);
        float var  = S2 * (1.f / 2048.f) - mean * mean;
        g_mean[bs] = mean;
        g_rstd[bs] = rsqrtf(var + 1e-6f);
    }
}

// ---------------------------------------------------------------------------
// GEMM1: 128m x 64od tile computing ALL THREE gates (igate/fgate/hidden),
// double-buffered smem, LN fused into A load, activations fused into epilogue.
// Writes g_f (sigmoid(fgate)) and g_cell (sigmoid(igate)*relu(hidden)).
// 256 threads, microtile 8m x 4od x 3 gates = 96 accumulators.
// ---------------------------------------------------------------------------
__global__ __launch_bounds__(256)
void gemm1_kernel(const float* __restrict__ heads,
                  const float* __restrict__ W,
                  const float* __restrict__ bias,
                  const float* __restrict__ lnw,
                  const float* __restrict__ lnb)
{
    __shared__ float As[2][16][128];
    __shared__ float Bs[2][3][16][64];

    int t  = threadIdx.x;
    int tx = t & 15;          // od quad: cols tx*4..tx*4+3
    int ty = t >> 4;          // m rows: ty*4..+3 and ty*4+64..+67
    int n0 = blockIdx.x * 64; // od base
    int m0 = blockIdx.y * 128;

    // LDG thread mapping
    int lrow = t >> 2;              // 0..63 (A rows, +64 for qq=1)
    int lkq  = (t & 3) << 2;        // k quad within 16
    int lsw  = lrow ^ (lkq << 1);   // swizzled column (A)
    int bo   = t >> 2;              // 0..63 (B rows = od)
    int bsw  = bo ^ (lkq << 2 >> 1);// = bo ^ (lkq<<1)
    bsw = bo ^ (lkq << 1);

    float acc[3][8][4];
    #pragma unroll
    for (int g = 0; g < 3; g++)
        #pragma unroll
        for (int i = 0; i < 8; i++)
            #pragma unroll
            for (int j = 0; j < 4; j++) acc[g][i][j] = 0.f;

    float4 av[2], bv[3];

    // ---- loader: fetch tile at k0 into registers ----
    auto ldg_tile = [&](int k0) {
        #pragma unroll
        for (int qq = 0; qq < 2; qq++) {
            int m = m0 + lrow + qq * 64;
            int k = k0 + lkq;
            float4 v;
            if (k < 256) {
                v = *(const float4*)(heads + (size_t)m * 256 + k);
            } else {
                int j = k - 256;
                v = *(const float4*)(g_csum + (size_t)m * 256 + j);
                int bs = m >> 3, h = m & 7;
                float mu = g_mean[bs], rs = g_rstd[bs];
                float4 w  = *(const float4*)(lnw + h * 256 + j);
                float4 bb = *(const float4*)(lnb + h * 256 + j);
                v.x = (v.x - mu) * rs * w.x + bb.x;
                v.y = (v.y - mu) * rs * w.y + bb.y;
                v.z = (v.z - mu) * rs * w.z + bb.z;
                v.w = (v.w - mu) * rs * w.w + bb.w;
            }
            av[qq] = v;
        }
        #pragma unroll
        for (int g = 0; g < 3; g++) {
            int og = g * 256 + n0 + bo;
            bv[g] = *(const float4*)(W + (size_t)og * Ktot + k0 + lkq);
        }
    };
    auto sts_tile = [&](int buf) {
        #pragma unroll
        for (int qq = 0; qq < 2; qq++) {
            int rs = (lrow + qq * 64) ^ (lkq << 1);
            As[buf][lkq + 0][rs] = av[qq].x;
            As[buf][lkq + 1][rs] = av[qq].y;
            As[buf][lkq + 2][rs] = av[qq].z;
            As[buf][lkq + 3][rs] = av[qq].w;
        }
        #pragma unroll
        for (int g = 0; g < 3; g++) {
            Bs[buf][g][lkq + 0][bsw] = bv[g].x;
            Bs[buf][g][lkq + 1][bsw] = bv[g].y;
            Bs[buf][g][lkq + 2][bsw] = bv[g].z;
            Bs[buf][g][lkq + 3][bsw] = bv[g].w;
        }
    };

    ldg_tile(0);
    sts_tile(0);
    __syncthreads();
    int cur = 0;

    for (int k0 = 0; k0 < Ktot; k0 += 16) {
        bool more = (k0 + 16 < Ktot);
        if (more) ldg_tile(k0 + 16);

        #pragma unroll
        for (int kk = 0; kk < 16; kk++) {
            int sw = swz(kk);
            float a[8], b[3][4];
            *(float4*)(a)     = *(const float4*)&As[cur][kk][(ty * 4)      ^ sw];
            *(float4*)(a + 4) = *(const float4*)&As[cur][kk][(ty * 4 + 64) ^ sw];
            #pragma unroll
            for (int g = 0; g < 3; g++)
                *(float4*)(b[g]) = *(const float4*)&Bs[cur][g][kk][(tx * 4) ^ sw];
            #pragma unroll
            for (int g = 0; g < 3; g++)
                #pragma unroll
                for (int i = 0; i < 8; i++)
                    #pragma unroll
                    for (int j = 0; j < 4; j++)
                        acc[g][i][j] = fmaf(a[i], b[g][j], acc[g][i][j]);
        }
        if (more) {
            sts_tile(cur ^ 1);
            __syncthreads();
            cur ^= 1;
        }
    }

    // epilogue: gate activations, write f and igh
    int od = n0 + tx * 4;
    float4 bi = *(const float4*)(bias + od);
    float4 bf = *(const float4*)(bias + 256 + od);
    float4 bh = *(const float4*)(bias + 512 + od);
    #pragma unroll
    for (int i = 0; i < 8; i++) {
        int m = m0 + ty * 4 + (i < 4 ? i : 60 + i);
        float4 f, ig;
        f.x = sigmoidf_(acc[1][i][0] + bf.x);
        f.y = sigmoidf_(acc[1][i][1] + bf.y);
        f.z = sigmoidf_(acc[1][i][2] + bf.z);
        f.w = sigmoidf_(acc[1][i][3] + bf.w);
        ig.x = sigmoidf_(acc[0][i][0] + bi.x) * fmaxf(acc[2][i][0] + bh.x, 0.f);
        ig.y = sigmoidf_(acc[0][i][1] + bi.y) * fmaxf(acc[2][i][1] + bh.y, 0.f);
        ig.z = sigmoidf_(acc[0][i][2] + bi.z) * fmaxf(acc[2][i][2] + bh.z, 0.f);
        ig.w = sigmoidf_(acc[0][i][3] + bi.w) * fmaxf(acc[2][i][3] + bh.w, 0.f);
        *(float4*)(g_f    + (size_t)m * 256 + od) = f;
        *(float4*)(g_cell + (size_t)m * 256 + od) = ig;
    }
}

// ---------------------------------------------------------------------------
// GEMM2: 128m x 128n, double-buffered, epilogue out = sigmoid(acc+b)*cell.
// A = [heads | cell]. 256 threads, 8x8 microtile (4+4 split both dims).
// ---------------------------------------------------------------------------
__global__ __launch_bounds__(256)
void gemm2_kernel(const float* __restrict__ heads,
                  const float* __restrict__ W,
                  const float* __restrict__ bias,
                  float* __restrict__ out)
{
    __shared__ float As[2][16][128];
    __shared__ float Bs[2][16][128];

    int t  = threadIdx.x;
    int tx = t & 15;
    int ty = t >> 4;
    int n0 = blockIdx.x * 128;
    int m0 = blockIdx.y * 128;

    int lrow = t >> 2;
    int lkq  = (t & 3) << 2;

    float acc[8][8];
    #pragma unroll
    for (int i = 0; i < 8; i++)
        #pragma unroll
        for (int j = 0; j < 8; j++) acc[i][j] = 0.f;

    float4 av[2], bv[2];

    auto ldg_tile = [&](int k0) {
        #pragma unroll
        for (int qq = 0; qq < 2; qq++) {
            int m = m0 + lrow + qq * 64;
            int k = k0 + lkq;
            if (k < 256)
                av[qq] = *(const float4*)(heads + (size_t)m * 256 + k);
            else
                av[qq] = *(const float4*)(g_cell + (size_t)m * 256 + (k - 256));
            int o = n0 + lrow + qq * 64;
            bv[qq] = *(const float4*)(W + (size_t)o * Ktot + k0 + lkq);
        }
    };
    auto sts_tile = [&](int buf) {
        #pragma unroll
        for (int qq = 0; qq < 2; qq++) {
            int rs = (lrow + qq * 64) ^ (lkq << 1);
            As[buf][lkq + 0][rs] = av[qq].x;
            As[buf][lkq + 1][rs] = av[qq].y;
            As[buf][lkq + 2][rs] = av[qq].z;
            As[buf][lkq + 3][rs] = av[qq].w;
            Bs[buf][lkq + 0][rs] = bv[qq].x;
            Bs[buf][lkq + 1][rs] = bv[qq].y;
            Bs[buf][lkq + 2][rs] = bv[qq].z;
            Bs[buf][lkq + 3][rs] = bv[qq].w;
        }
    };

    ldg_tile(0);
    sts_tile(0);
    __syncthreads();
    int cur = 0;

    for (int k0 = 0; k0 < Ktot; k0 += 16) {
        bool more = (k0 + 16 < Ktot);
        if (more) ldg_tile(k0 + 16);

        #pragma unroll
        for (int kk = 0; kk < 16; kk++) {
            int sw = swz(kk);
            float a[8], b[8];
            *(float4*)(a)     = *(const float4*)&As[cur][kk][(ty * 4)      ^ sw];
            *(float4*)(a + 4) = *(const float4*)&As[cur][kk][(ty * 4 + 64) ^ sw];
            *(float4*)(b)     = *(const float4*)&Bs[cur][kk][(tx * 4)      ^ sw];
            *(float4*)(b + 4) = *(const float4*)&Bs[cur][kk][(tx * 4 + 64) ^ sw];
            #pragma unroll
            for (int i = 0; i < 8; i++)
                #pragma unroll
                for (int j = 0; j < 8; j++)
                    acc[i][j] = fmaf(a[i], b[j], acc[i][j]);
        }
        if (more) {
            sts_tile(cur ^ 1);
            __syncthreads();
            cur ^= 1;
        }
    }

    // epilogue
    #pragma unroll
    for (int jj = 0; jj < 2; jj++) {
        int o0 = n0 + tx * 4 + jj * 64;
        float4 bb = *(const float4*)(bias + o0);
        #pragma unroll
        for (int i = 0; i < 8; i++) {
            int m = m0 + ty * 4 + (i < 4 ? i : 60 + i);
            float4 c = *(const float4*)(g_cell + (size_t)m * 256 + o0);
            float4 v;
            v.x = sigmoidf_(acc[i][jj * 4 + 0] + bb.x) * c.x;
            v.y = sigmoidf_(acc[i][jj * 4 + 1] + bb.y) * c.y;
            v.z = sigmoidf_(acc[i][jj * 4 + 2] + bb.z) * c.z;
            v.w = sigmoidf_(acc[i][jj * 4 + 3] + bb.w) * c.w;
            *(float4*)(out + (size_t)m * 256 + o0) = v;
        }
    }
}

// ---------------------------------------------------------------------------
// Scan: c <- f*c + igh over S (associative blocked scan). Writes cell in-place.
// ---------------------------------------------------------------------------
__global__ void scan_kernel(const float* __restrict__ init_cx) {
    int lane = threadIdx.x;
    int r    = threadIdx.y;
    int idt  = blockIdx.x & 7;
    int h    = (blockIdx.x >> 3) & 7;
    int b    = blockIdx.x >> 6;
    int od   = idt * 32 + lane;
    size_t base = (size_t)b * Ssz * SSTRIDE + (size_t)h * ODsz + od;
    const int CH = Ssz / 16;

    size_t p = base + (size_t)(r * CH) * SSTRIDE;
    float F = 1.f, I = 0.f;
    for (int i = 0; i < CH; i++) {
        float f = g_f[p], ig = g_cell[p];
        I = fmaf(f, I, ig);
        F *= f;
        p += SSTRIDE;
    }
    __shared__ float sF[16][32], sI[16][32];
    sF[r][lane] = F; sI[r][lane] = I;
    __syncthreads();
    if (r == 0) {
        float c = init_cx[h * 256 + od];
        #pragma unroll
        for (int k2 = 0; k2 < 16; k2++) {
            float nf = sF[k2][lane], ni = sI[k2][lane];
            sI[k2][lane] = c;
            c = fmaf(nf, c, ni);
        }
    }
    __syncthreads();
    float c = sI[r][lane];
    p = base + (size_t)(r * CH) * SSTRIDE;
    for (int i = 0; i < CH; i++) {
        float f = g_f[p], ig = g_cell[p];
        c = fmaf(f, c, ig);
        g_cell[p] = c;
        p += SSTRIDE;
    }
}

// ---------------------------------------------------------------------------
extern "C" void kernel_launch(void* const* d_in, const int* in_sizes, int n_in,
                              void* d_out, int out_size)
{
    const float* heads   = (const float*)d_in[0];
    const float* W_hid   = (const float*)d_in[1];
    const float* b_hid   = (const float*)d_in[2];
    const float* W_og    = (const float*)d_in[3];
    const float* b_og    = (const float*)d_in[4];
    const float* ln_w    = (const float*)d_in[5];
    const float* ln_b    = (const float*)d_in[6];
    const float* init_cx = (const float*)d_in[7];
    float* out = (float*)d_out;

    cumsum_kernel<<<512, dim3(32, 16)>>>(heads);
    stats_kernel<<<BSN, 256>>>();
    gemm1_kernel<<<dim3(4, Mrows / 128), 256>>>(heads, W_hid, b_hid, ln_w, ln_b);
    scan_kernel<<<512, dim3(32, 16)>>>(init_cx);
    gemm2_kernel<<<dim3(2, Mrows / 128), 256>>>(heads, W_og, b_og, out);
}

// round 4
// speedup vs baseline: 1.0943x; 1.0228x over previous
#include <cuda_runtime.h>
#include <math.h>

// Problem constants
#define Bsz   8
#define Ssz   2048
#define Hsz   8
#define IDsz  256
#define ODsz  256
#define Mrows (Bsz*Ssz*Hsz)    // 131072 rows (b,s,h)
#define Ktot  512              // 2*ID = ID+OD
#define BSN   (Bsz*Ssz)        // 16384 (b,s) pairs
#define SSTRIDE 2048           // H*ID floats between consecutive s

typedef unsigned long long ull;

// Scratch (device globals: allocation-free per harness rules)
__device__ float g_csum[(size_t)Mrows*IDsz];   // 134 MB
__device__ float g_f  [(size_t)Mrows*ODsz];    // 134 MB
__device__ float g_cell[(size_t)Mrows*ODsz];   // 134 MB
__device__ float g_mean[BSN];
__device__ float g_rstd[BSN];

__device__ __forceinline__ float sigmoidf_(float x) {
    return 1.0f / (1.0f + __expf(-x));
}

// packed fp32x2 helpers (FFMA2 path — ptxas never auto-fuses)
#define FMA2(acc, a, b) \
    asm("fma.rn.f32x2 %0, %1, %2, %0;" : "+l"(acc) : "l"(a), "l"(b))
__device__ __forceinline__ ull dupf(float x) {
    ull d;
    asm("mov.b64 %0, {%1, %1};" : "=l"(d) : "f"(x));
    return d;
}
__device__ __forceinline__ float2 unpk(ull d) {
    float lo, hi;
    asm("mov.b64 {%0, %1}, %2;" : "=f"(lo), "=f"(hi) : "l"(d));
    return make_float2(lo, hi);
}

union D2F4 { float4 f4; ull u[2]; };

// smem column swizzle (conflict-free transpose STS + aligned float4 LDS)
__device__ __forceinline__ int swz(int kk) { return (kk & 12) << 1; }

// ---------------------------------------------------------------------------
// Kernel 1: cumsum over S per (b,h,id).
// ---------------------------------------------------------------------------
__global__ void cumsum_kernel(const float* __restrict__ x) {
    int lane = threadIdx.x;
    int r    = threadIdx.y;
    int idt  = blockIdx.x & 7;
    int h    = (blockIdx.x >> 3) & 7;
    int b    = blockIdx.x >> 6;
    int id   = idt * 32 + lane;
    size_t base = (size_t)b * Ssz * SSTRIDE + (size_t)h * IDsz + id;
    const int CH = Ssz / 16;

    size_t p = base + (size_t)(r * CH) * SSTRIDE;
    float sum = 0.f;
    for (int i = 0; i < CH; i++) { sum += x[p]; p += SSTRIDE; }

    __shared__ float cs[16][32];
    cs[r][lane] = sum;
    __syncthreads();
    if (r == 0) {
        float a = 0.f;
        #pragma unroll
        for (int k2 = 0; k2 < 16; k2++) { float v = cs[k2][lane]; cs[k2][lane] = a; a += v; }
    }
    __syncthreads();

    float run = cs[r][lane];
    p = base + (size_t)(r * CH) * SSTRIDE;
    for (int i = 0; i < CH; i++) { run += x[p]; g_csum[p] = run; p += SSTRIDE; }
}

// ---------------------------------------------------------------------------
// Kernel 2: LayerNorm stats per (b,s).
// ---------------------------------------------------------------------------
__global__ void stats_kernel() {
    int bs = blockIdx.x;
    const float4* p = (const float4*)(g_csum + (size_t)bs * 2048);
    float s = 0.f, ss = 0.f;
    for (int i = threadIdx.x; i < 512; i += 256) {
        float4 v = p[i];
        s  += v.x + v.y + v.z + v.w;
        ss += v.x*v.x + v.y*v.y + v.z*v.z + v.w*v.w;
    }
    #pragma unroll
    for (int o = 16; o; o >>= 1) {
        s  += __shfl_down_sync(0xffffffffu, s,  o);
        ss += __shfl_down_sync(0xffffffffu, ss, o);
    }
    __shared__ float ws[8], wss[8];
    int wid = threadIdx.x >> 5, lane = threadIdx.x & 31;
    if (lane == 0) { ws[wid] = s; wss[wid] = ss; }
    __syncthreads();
    if (threadIdx.x == 0) {
        float S1 = 0.f, S2 = 0.f;
        #pragma unroll
        for (int i = 0; i < 8; i++) { S1 += ws[i]; S2 += wss[i]; }
        float mean = S1 * (1.f / 2048.f);
        float var  = S2 * (1.f / 2048.f) - mean * mean;
        g_mean[bs] = mean;
        g_rstd[bs] = rsqrtf(var + 1e-6f);
    }
}

// ---------------------------------------------------------------------------
// GEMM1: 128m x 64od x 3gates, FFMA2 inner loop (acc packed along od pairs),
// double-buffered, LN fused into A load, gate activations in epilogue.
// ---------------------------------------------------------------------------
__global__ __launch_bounds__(256)
void gemm1_kernel(const float* __restrict__ heads,
                  const float* __restrict__ W,
                  const float* __restrict__ bias,
                  const float* __restrict__ lnw,
                  const float* __restrict__ lnb)
{
    __shared__ float As[2][16][128];
    __shared__ float Bs[2][3][16][64];

    int t  = threadIdx.x;
    int tx = t & 15;          // od quad base: tx*4
    int ty = t >> 4;          // m rows ty*4.. and ty*4+64..
    int n0 = blockIdx.x * 64;
    int m0 = blockIdx.y * 128;

    int lrow = t >> 2;
    int lkq  = (t & 3) << 2;
    int bsw  = lrow ^ (lkq << 1);

    // acc[g][i][jp]: gate g, m-row i (0..7), od pair jp (0..1)
    ull acc[3][8][2];
    #pragma unroll
    for (int g = 0; g < 3; g++)
        #pragma unroll
        for (int i = 0; i < 8; i++)
            { acc[g][i][0] = 0ull; acc[g][i][1] = 0ull; }

    float4 av[2], bv[3];

    auto ldg_tile = [&](int k0) {
        #pragma unroll
        for (int qq = 0; qq < 2; qq++) {
            int m = m0 + lrow + qq * 64;
            int k = k0 + lkq;
            float4 v;
            if (k < 256) {
                v = *(const float4*)(heads + (size_t)m * 256 + k);
            } else {
                int j = k - 256;
                v = *(const float4*)(g_csum + (size_t)m * 256 + j);
                int bs = m >> 3, h = m & 7;
                float mu = g_mean[bs], rs = g_rstd[bs];
                float4 w  = *(const float4*)(lnw + h * 256 + j);
                float4 bb = *(const float4*)(lnb + h * 256 + j);
                v.x = (v.x - mu) * rs * w.x + bb.x;
                v.y = (v.y - mu) * rs * w.y + bb.y;
                v.z = (v.z - mu) * rs * w.z + bb.z;
                v.w = (v.w - mu) * rs * w.w + bb.w;
            }
            av[qq] = v;
        }
        #pragma unroll
        for (int g = 0; g < 3; g++) {
            int og = g * 256 + n0 + lrow;
            bv[g] = *(const float4*)(W + (size_t)og * Ktot + k0 + lkq);
        }
    };
    auto sts_tile = [&](int buf) {
        #pragma unroll
        for (int qq = 0; qq < 2; qq++) {
            int rs = (lrow + qq * 64) ^ (lkq << 1);
            As[buf][lkq + 0][rs] = av[qq].x;
            As[buf][lkq + 1][rs] = av[qq].y;
            As[buf][lkq + 2][rs] = av[qq].z;
            As[buf][lkq + 3][rs] = av[qq].w;
        }
        #pragma unroll
        for (int g = 0; g < 3; g++) {
            Bs[buf][g][lkq + 0][bsw] = bv[g].x;
            Bs[buf][g][lkq + 1][bsw] = bv[g].y;
            Bs[buf][g][lkq + 2][bsw] = bv[g].z;
            Bs[buf][g][lkq + 3][bsw] = bv[g].w;
        }
    };

    ldg_tile(0);
    sts_tile(0);
    __syncthreads();
    int cur = 0;

    for (int k0 = 0; k0 < Ktot; k0 += 16) {
        bool more = (k0 + 16 < Ktot);
        if (more) ldg_tile(k0 + 16);

        #pragma unroll
        for (int kk = 0; kk < 16; kk++) {
            int sw = swz(kk);
            D2F4 A0, A1, B[3];
            A0.f4 = *(const float4*)&As[cur][kk][(ty * 4)      ^ sw];
            A1.f4 = *(const float4*)&As[cur][kk][(ty * 4 + 64) ^ sw];
            #pragma unroll
            for (int g = 0; g < 3; g++)
                B[g].f4 = *(const float4*)&Bs[cur][g][kk][(tx * 4) ^ sw];
            // duplicate A scalars into both f32x2 halves
            ull ad[8];
            ad[0] = dupf(A0.f4.x); ad[1] = dupf(A0.f4.y);
            ad[2] = dupf(A0.f4.z); ad[3] = dupf(A0.f4.w);
            ad[4] = dupf(A1.f4.x); ad[5] = dupf(A1.f4.y);
            ad[6] = dupf(A1.f4.z); ad[7] = dupf(A1.f4.w);
            #pragma unroll
            for (int g = 0; g < 3; g++)
                #pragma unroll
                for (int i = 0; i < 8; i++) {
                    FMA2(acc[g][i][0], ad[i], B[g].u[0]);
                    FMA2(acc[g][i][1], ad[i], B[g].u[1]);
                }
        }
        if (more) {
            sts_tile(cur ^ 1);
            __syncthreads();
            cur ^= 1;
        }
    }

    // epilogue: gate activations
    int od = n0 + tx * 4;
    float4 bi = *(const float4*)(bias + od);
    float4 bf = *(const float4*)(bias + 256 + od);
    float4 bh = *(const float4*)(bias + 512 + od);
    #pragma unroll
    for (int i = 0; i < 8; i++) {
        int m = m0 + ty * 4 + (i < 4 ? i : 60 + i);
        float2 i0 = unpk(acc[0][i][0]), i1 = unpk(acc[0][i][1]);
        float2 f0 = unpk(acc[1][i][0]), f1 = unpk(acc[1][i][1]);
        float2 h0 = unpk(acc[2][i][0]), h1 = unpk(acc[2][i][1]);
        float4 f, ig;
        f.x = sigmoidf_(f0.x + bf.x);
        f.y = sigmoidf_(f0.y + bf.y);
        f.z = sigmoidf_(f1.x + bf.z);
        f.w = sigmoidf_(f1.y + bf.w);
        ig.x = sigmoidf_(i0.x + bi.x) * fmaxf(h0.x + bh.x, 0.f);
        ig.y = sigmoidf_(i0.y + bi.y) * fmaxf(h0.y + bh.y, 0.f);
        ig.z = sigmoidf_(i1.x + bi.z) * fmaxf(h1.x + bh.z, 0.f);
        ig.w = sigmoidf_(i1.y + bi.w) * fmaxf(h1.y + bh.w, 0.f);
        *(float4*)(g_f    + (size_t)m * 256 + od) = f;
        *(float4*)(g_cell + (size_t)m * 256 + od) = ig;
    }
}

// ---------------------------------------------------------------------------
// GEMM2: 128m x 128n, FFMA2 inner loop, epilogue out = sigmoid(acc+b)*cell.
// ---------------------------------------------------------------------------
__global__ __launch_bounds__(256)
void gemm2_kernel(const float* __restrict__ heads,
                  const float* __restrict__ W,
                  const float* __restrict__ bias,
                  float* __restrict__ out)
{
    __shared__ float As[2][16][128];
    __shared__ float Bs[2][16][128];

    int t  = threadIdx.x;
    int tx = t & 15;
    int ty = t >> 4;
    int n0 = blockIdx.x * 128;
    int m0 = blockIdx.y * 128;

    int lrow = t >> 2;
    int lkq  = (t & 3) << 2;

    // acc[i][jp]: m-row i (0..7), od pair jp (0..3); jp 0,1 -> tx*4, jp 2,3 -> tx*4+64
    ull acc[8][4];
    #pragma unroll
    for (int i = 0; i < 8; i++)
        #pragma unroll
        for (int j = 0; j < 4; j++) acc[i][j] = 0ull;

    float4 av[2], bv[2];

    auto ldg_tile = [&](int k0) {
        #pragma unroll
        for (int qq = 0; qq < 2; qq++) {
            int m = m0 + lrow + qq * 64;
            int k = k0 + lkq;
            if (k < 256)
                av[qq] = *(const float4*)(heads + (size_t)m * 256 + k);
            else
                av[qq] = *(const float4*)(g_cell + (size_t)m * 256 + (k - 256));
            int o = n0 + lrow + qq * 64;
            bv[qq] = *(const float4*)(W + (size_t)o * Ktot + k0 + lkq);
        }
    };
    auto sts_tile = [&](int buf) {
        #pragma unroll
        for (int qq = 0; qq < 2; qq++) {
            int rs = (lrow + qq * 64) ^ (lkq << 1);
            As[buf][lkq + 0][rs] = av[qq].x;
            As[buf][lkq + 1][rs] = av[qq].y;
            As[buf][lkq + 2][rs] = av[qq].z;
            As[buf][lkq + 3][rs] = av[qq].w;
            Bs[buf][lkq + 0][rs] = bv[qq].x;
            Bs[buf][lkq + 1][rs] = bv[qq].y;
            Bs[buf][lkq + 2][rs] = bv[qq].z;
            Bs[buf][lkq + 3][rs] = bv[qq].w;
        }
    };

    ldg_tile(0);
    sts_tile(0);
    __syncthreads();
    int cur = 0;

    for (int k0 = 0; k0 < Ktot; k0 += 16) {
        bool more = (k0 + 16 < Ktot);
        if (more) ldg_tile(k0 + 16);

        #pragma unroll
        for (int kk = 0; kk < 16; kk++) {
            int sw = swz(kk);
            D2F4 A0, A1, B0, B1;
            A0.f4 = *(const float4*)&As[cur][kk][(ty * 4)      ^ sw];
            A1.f4 = *(const float4*)&As[cur][kk][(ty * 4 + 64) ^ sw];
            B0.f4 = *(const float4*)&Bs[cur][kk][(tx * 4)      ^ sw];
            B1.f4 = *(const float4*)&Bs[cur][kk][(tx * 4 + 64) ^ sw];
            ull ad[8];
            ad[0] = dupf(A0.f4.x); ad[1] = dupf(A0.f4.y);
            ad[2] = dupf(A0.f4.z); ad[3] = dupf(A0.f4.w);
            ad[4] = dupf(A1.f4.x); ad[5] = dupf(A1.f4.y);
            ad[6] = dupf(A1.f4.z); ad[7] = dupf(A1.f4.w);
            #pragma unroll
            for (int i = 0; i < 8; i++) {
                FMA2(acc[i][0], ad[i], B0.u[0]);
                FMA2(acc[i][1], ad[i], B0.u[1]);
                FMA2(acc[i][2], ad[i], B1.u[0]);
                FMA2(acc[i][3], ad[i], B1.u[1]);
            }
        }
        if (more) {
            sts_tile(cur ^ 1);
            __syncthreads();
            cur ^= 1;
        }
    }

    // epilogue
    #pragma unroll
    for (int jj = 0; jj < 2; jj++) {
        int o0 = n0 + tx * 4 + jj * 64;
        float4 bb = *(const float4*)(bias + o0);
        #pragma unroll
        for (int i = 0; i < 8; i++) {
            int m = m0 + ty * 4 + (i < 4 ? i : 60 + i);
            float2 p0 = unpk(acc[i][jj * 2 + 0]);
            float2 p1 = unpk(acc[i][jj * 2 + 1]);
            float4 c = *(const float4*)(g_cell + (size_t)m * 256 + o0);
            float4 v;
            v.x = sigmoidf_(p0.x + bb.x) * c.x;
            v.y = sigmoidf_(p0.y + bb.y) * c.y;
            v.z = sigmoidf_(p1.x + bb.z) * c.z;
            v.w = sigmoidf_(p1.y + bb.w) * c.w;
            *(float4*)(out + (size_t)m * 256 + o0) = v;
        }
    }
}

// ---------------------------------------------------------------------------
// Scan: c <- f*c + igh over S (associative blocked scan).
// ---------------------------------------------------------------------------
__global__ void scan_kernel(const float* __restrict__ init_cx) {
    int lane = threadIdx.x;
    int r    = threadIdx.y;
    int idt  = blockIdx.x & 7;
    int h    = (blockIdx.x >> 3) & 7;
    int b    = blockIdx.x >> 6;
    int od   = idt * 32 + lane;
    size_t base = (size_t)b * Ssz * SSTRIDE + (size_t)h * ODsz + od;
    const int CH = Ssz / 16;

    size_t p = base + (size_t)(r * CH) * SSTRIDE;
    float F = 1.f, I = 0.f;
    for (int i = 0; i < CH; i++) {
        float f = g_f[p], ig = g_cell[p];
        I = fmaf(f, I, ig);
        F *= f;
        p += SSTRIDE;
    }
    __shared__ float sF[16][32], sI[16][32];
    sF[r][lane] = F; sI[r][lane] = I;
    __syncthreads();
    if (r == 0) {
        float c = init_cx[h * 256 + od];
        #pragma unroll
        for (int k2 = 0; k2 < 16; k2++) {
            float nf = sF[k2][lane], ni = sI[k2][lane];
            sI[k2][lane] = c;
            c = fmaf(nf, c, ni);
        }
    }
    __syncthreads();
    float c = sI[r][lane];
    p = base + (size_t)(r * CH) * SSTRIDE;
    for (int i = 0; i < CH; i++) {
        float f = g_f[p], ig = g_cell[p];
        c = fmaf(f, c, ig);
        g_cell[p] = c;
        p += SSTRIDE;
    }
}

// ---------------------------------------------------------------------------
extern "C" void kernel_launch(void* const* d_in, const int* in_sizes, int n_in,
                              void* d_out, int out_size)
{
    const float* heads   = (const float*)d_in[0];
    const float* W_hid   = (const float*)d_in[1];
    const float* b_hid   = (const float*)d_in[2];
    const float* W_og    = (const float*)d_in[3];
    const float* b_og    = (const float*)d_in[4];
    const float* ln_w    = (const float*)d_in[5];
    const float* ln_b    = (const float*)d_in[6];
    const float* init_cx = (const float*)d_in[7];
    float* out = (float*)d_out;

    cumsum_kernel<<<512, dim3(32, 16)>>>(heads);
    stats_kernel<<<BSN, 256>>>();
    gemm1_kernel<<<dim3(4, Mrows / 128), 256>>>(heads, W_hid, b_hid, ln_w, ln_b);
    scan_kernel<<<512, dim3(32, 16)>>>(init_cx);
    gemm2_kernel<<<dim3(2, Mrows / 128), 256>>>(heads, W_og, b_og, out);
}

// round 10
// speedup vs baseline: 2.3619x; 2.1584x over previous
#include <cuda_runtime.h>
#include <math.h>
#include <stdint.h>

// Problem constants
#define Bsz   8
#define Ssz   2048
#define Hsz   8
#define Mrows (Bsz*Ssz*Hsz)    // 131072 rows (b,s,h)
#define Ktot  512
#define BSN   (Bsz*Ssz)
#define SSTRIDE 2048

// Scratch
__device__ float g_csum[(size_t)Mrows*256];
__device__ float g_f  [(size_t)Mrows*256];
__device__ float g_cell[(size_t)Mrows*256];
__device__ float g_Wp [768*512];          // repacked W_hid: [ob*192 + gate*64 + odl]
__device__ float g_mean[BSN];
__device__ float g_rstd[BSN];

__device__ __forceinline__ float sigmoidf_(float x) {
    return 1.0f / (1.0f + __expf(-x));
}
__device__ __forceinline__ uint32_t f2tf(float x) {
    uint32_t u;
    asm("cvt.rna.tf32.f32 %0, %1;" : "=r"(u) : "f"(x));
    return u;
}
#define MMA_TF32(d, a, b0, b1) \
    asm volatile("mma.sync.aligned.m16n8k8.row.col.f32.tf32.tf32.f32 " \
        "{%0,%1,%2,%3}, {%4,%5,%6,%7}, {%8,%9}, {%0,%1,%2,%3};" \
        : "+f"(d[0]), "+f"(d[1]), "+f"(d[2]), "+f"(d[3]) \
        : "r"(a[0]), "r"(a[1]), "r"(a[2]), "r"(a[3]), "r"(b0), "r"(b1))

// ---------------------------------------------------------------------------
// cumsum over S per (b,h,id)
// ---------------------------------------------------------------------------
__global__ void cumsum_kernel(const float* __restrict__ x) {
    int lane = threadIdx.x;
    int r    = threadIdx.y;
    int idt  = blockIdx.x & 7;
    int h    = (blockIdx.x >> 3) & 7;
    int b    = blockIdx.x >> 6;
    int id   = idt * 32 + lane;
    size_t base = (size_t)b * Ssz * SSTRIDE + (size_t)h * 256 + id;
    const int CH = Ssz / 16;

    size_t p = base + (size_t)(r * CH) * SSTRIDE;
    float sum = 0.f;
    for (int i = 0; i < CH; i++) { sum += x[p]; p += SSTRIDE; }

    __shared__ float cs[16][32];
    cs[r][lane] = sum;
    __syncthreads();
    if (r == 0) {
        float a = 0.f;
        #pragma unroll
        for (int k2 = 0; k2 < 16; k2++) { float v = cs[k2][lane]; cs[k2][lane] = a; a += v; }
    }
    __syncthreads();

    float run = cs[r][lane];
    p = base + (size_t)(r * CH) * SSTRIDE;
    for (int i = 0; i < CH; i++) { run += x[p]; g_csum[p] = run; p += SSTRIDE; }
}

// ---------------------------------------------------------------------------
// LayerNorm stats per (b,s)
// ---------------------------------------------------------------------------
__global__ void stats_kernel() {
    int bs = blockIdx.x;
    const float4* p = (const float4*)(g_csum + (size_t)bs * 2048);
    float s = 0.f, ss = 0.f;
    for (int i = threadIdx.x; i < 512; i += 256) {
        float4 v = p[i];
        s  += v.x + v.y + v.z + v.w;
        ss += v.x*v.x + v.y*v.y + v.z*v.z + v.w*v.w;
    }
    #pragma unroll
    for (int o = 16; o; o >>= 1) {
        s  += __shfl_down_sync(0xffffffffu, s,  o);
        ss += __shfl_down_sync(0xffffffffu, ss, o);
    }
    __shared__ float ws[8], wss[8];
    int wid = threadIdx.x >> 5, lane = threadIdx.x & 31;
    if (lane == 0) { ws[wid] = s; wss[wid] = ss; }
    __syncthreads();
    if (threadIdx.x == 0) {
        float S1 = 0.f, S2 = 0.f;
        #pragma unroll
        for (int i = 0; i < 8; i++) { S1 += ws[i]; S2 += wss[i]; }
        float mean = S1 * (1.f / 2048.f);
        float var  = S2 * (1.f / 2048.f) - mean * mean;
        g_mean[bs] = mean;
        g_rstd[bs] = rsqrtf(var + 1e-6f);
    }
}

// ---------------------------------------------------------------------------
// Repack W_hid: Wp[ob*192 + gate*64 + odl] = W_hid[gate*256 + ob*64 + odl]
// ---------------------------------------------------------------------------
__global__ void repack_kernel(const float* __restrict__ W) {
    int r = blockIdx.x;               // dest row 0..767
    int ob = r / 192, rem = r % 192;
    int gate = rem / 64, odl = rem % 64;
    int src = gate * 256 + ob * 64 + odl;
    const float4* s = (const float4*)(W + (size_t)src * 512);
    float4* d = (float4*)(g_Wp + (size_t)r * 512);
    d[threadIdx.x] = s[threadIdx.x];
}

// ---------------------------------------------------------------------------
// GEMM1 (mma.sync tf32): CTA 128m x 192n = {i|f|h} x 64 od.
// A = [heads | LN(csum)] fused at load. Smem-staged epilogue -> g_f, g_cell.
// 8 warps: wm(2) x wn(4); warp tile 64m x 48n; frags 4m x 6n.
// ---------------------------------------------------------------------------
#define G1_SMEM 102400
__global__ __launch_bounds__(256)
void gemm1_t(const float* __restrict__ heads,
             const float* __restrict__ bias,
             const float* __restrict__ lnw,
             const float* __restrict__ lnb)
{
    extern __shared__ char smem[];
    uint32_t* As = (uint32_t*)smem;                 // 2 x 128x32
    uint32_t* Bs = (uint32_t*)(smem + 32768);       // 2 x 192x32
    float* stage = (float*)smem;                    // 128 x 200

    int t = threadIdx.x, w = t >> 5, lane = t & 31;
    int g = lane >> 2, tg = lane & 3;
    int wm = w >> 2, wn = w & 3;
    int ob = blockIdx.x;                 // od block 0..3
    int m0 = blockIdx.y * 128;
    int nbase = ob * 192;

    float acc[4][6][4];
    #pragma unroll
    for (int i = 0; i < 4; i++)
        #pragma unroll
        for (int j = 0; j < 6; j++)
            #pragma unroll
            for (int k = 0; k < 4; k++) acc[i][j][k] = 0.f;

    float4 areg[4], breg[6];

    auto ldg = [&](int c) {
        int k0 = c * 32;
        #pragma unroll
        for (int q = 0; q < 4; q++) {
            int gid = t + q * 256, row = gid >> 3, qc = gid & 7;
            int m = m0 + row;
            if (k0 < 256) {
                areg[q] = *(const float4*)(heads + (size_t)m * 256 + k0 + qc * 4);
            } else {
                int j = k0 - 256 + qc * 4;
                float4 v = *(const float4*)(g_csum + (size_t)m * 256 + j);
                int bs = m >> 3, h = m & 7;
                float mu = g_mean[bs], rs = g_rstd[bs];
                float4 wv = *(const float4*)(lnw + h * 256 + j);
                float4 bb = *(const float4*)(lnb + h * 256 + j);
                v.x = (v.x - mu) * rs * wv.x + bb.x;
                v.y = (v.y - mu) * rs * wv.y + bb.y;
                v.z = (v.z - mu) * rs * wv.z + bb.z;
                v.w = (v.w - mu) * rs * wv.w + bb.w;
                areg[q] = v;
            }
        }
        #pragma unroll
        for (int q = 0; q < 6; q++) {
            int gid = t + q * 256, row = gid >> 3, qc = gid & 7;
            breg[q] = *(const float4*)(g_Wp + (size_t)(nbase + row) * 512 + k0 + qc * 4);
        }
    };
    auto sts = [&](int buf) {
        #pragma unroll
        for (int q = 0; q < 4; q++) {
            int gid = t + q * 256, row = gid >> 3, qc = gid & 7;
            uint32_t* d = As + buf * 4096 + row * 32 + ((qc ^ (row & 7)) << 2);
            d[0] = f2tf(areg[q].x); d[1] = f2tf(areg[q].y);
            d[2] = f2tf(areg[q].z); d[3] = f2tf(areg[q].w);
        }
        #pragma unroll
        for (int q = 0; q < 6; q++) {
            int gid = t + q * 256, row = gid >> 3, qc = gid & 7;
            uint32_t* d = Bs + buf * 6144 + row * 32 + ((qc ^ (row & 7)) << 2);
            d[0] = f2tf(breg[q].x); d[1] = f2tf(breg[q].y);
            d[2] = f2tf(breg[q].z); d[3] = f2tf(breg[q].w);
        }
    };

    ldg(0); sts(0);
    __syncthreads();
    int cur = 0;

    for (int c = 0; c < 16; c++) {
        bool more = (c < 15);
        if (more) ldg(c + 1);
        const uint32_t* Ab = As + cur * 4096;
        const uint32_t* Bb = Bs + cur * 6144;
        #pragma unroll
        for (int ks = 0; ks < 4; ks++) {
            int c0 = (((2 * ks)     ^ g) << 2) + tg;
            int c1 = (((2 * ks + 1) ^ g) << 2) + tg;
            uint32_t af[4][4];
            #pragma unroll
            for (int fm = 0; fm < 4; fm++) {
                int base = (wm * 64 + fm * 16 + g) * 32;
                af[fm][0] = Ab[base + c0];
                af[fm][1] = Ab[base + 256 + c0];
                af[fm][2] = Ab[base + c1];
                af[fm][3] = Ab[base + 256 + c1];
            }
            #pragma unroll
            for (int fn = 0; fn < 6; fn++) {
                int nb = (wn * 48 + fn * 8 + g) * 32;
                uint32_t b0 = Bb[nb + c0], b1 = Bb[nb + c1];
                #pragma unroll
                for (int fm = 0; fm < 4; fm++)
                    MMA_TF32(acc[fm][fn], af[fm], b0, b1);
            }
        }
        if (more) {
            sts(cur ^ 1);
            __syncthreads();
            cur ^= 1;
        }
    }

    // stage D to smem
    __syncthreads();
    #pragma unroll
    for (int fm = 0; fm < 4; fm++) {
        int r0 = wm * 64 + fm * 16 + g;
        #pragma unroll
        for (int fn = 0; fn < 6; fn++) {
            int col = wn * 48 + fn * 8 + 2 * tg;
            *(float2*)&stage[r0 * 200 + col]       = make_float2(acc[fm][fn][0], acc[fm][fn][1]);
            *(float2*)&stage[(r0 + 8) * 200 + col] = make_float2(acc[fm][fn][2], acc[fm][fn][3]);
        }
    }
    __syncthreads();

    // epilogue: gates -> activations
    int row = t >> 1, half = (t & 1) * 32;
    int m = m0 + row;
    const float* sr = stage + row * 200;
    #pragma unroll
    for (int j = 0; j < 32; j += 4) {
        int odl = half + j;
        int od = ob * 64 + odl;
        float4 iv = *(const float4*)(sr + odl);
        float4 fv = *(const float4*)(sr + 64 + odl);
        float4 hv = *(const float4*)(sr + 128 + odl);
        float4 bi = *(const float4*)(bias + od);
        float4 bf = *(const float4*)(bias + 256 + od);
        float4 bh = *(const float4*)(bias + 512 + od);
        float4 fo, ig;
        fo.x = sigmoidf_(fv.x + bf.x);
        fo.y = sigmoidf_(fv.y + bf.y);
        fo.z = sigmoidf_(fv.z + bf.z);
        fo.w = sigmoidf_(fv.w + bf.w);
        ig.x = sigmoidf_(iv.x + bi.x) * fmaxf(hv.x + bh.x, 0.f);
        ig.y = sigmoidf_(iv.y + bi.y) * fmaxf(hv.y + bh.y, 0.f);
        ig.z = sigmoidf_(iv.z + bi.z) * fmaxf(hv.z + bh.z, 0.f);
        ig.w = sigmoidf_(iv.w + bi.w) * fmaxf(hv.w + bh.w, 0.f);
        *(float4*)(g_f    + (size_t)m * 256 + od) = fo;
        *(float4*)(g_cell + (size_t)m * 256 + od) = ig;
    }
}

// ---------------------------------------------------------------------------
// GEMM2 (mma.sync tf32): CTA 128m x 128n, epilogue out = sigmoid(D+b)*cell.
// 8 warps: wm(2) x wn(4); warp tile 64m x 32n; frags 4m x 4n.
// ---------------------------------------------------------------------------
#define G2_SMEM 69632
__global__ __launch_bounds__(256)
void gemm2_t(const float* __restrict__ heads,
             const float* __restrict__ W,
             const float* __restrict__ bias,
             float* __restrict__ out)
{
    extern __shared__ char smem[];
    uint32_t* As = (uint32_t*)smem;                 // 2 x 128x32
    uint32_t* Bs = (uint32_t*)(smem + 32768);       // 2 x 128x32
    float* stage = (float*)smem;                    // 128 x 136

    int t = threadIdx.x, w = t >> 5, lane = t & 31;
    int g = lane >> 2, tg = lane & 3;
    int wm = w >> 2, wn = w & 3;
    int n0 = blockIdx.x * 128;
    int m0 = blockIdx.y * 128;

    float acc[4][4][4];
    #pragma unroll
    for (int i = 0; i < 4; i++)
        #pragma unroll
        for (int j = 0; j < 4; j++)
            #pragma unroll
            for (int k = 0; k < 4; k++) acc[i][j][k] = 0.f;

    float4 areg[4], breg[4];

    auto ldg = [&](int c) {
        int k0 = c * 32;
        #pragma unroll
        for (int q = 0; q < 4; q++) {
            int gid = t + q * 256, row = gid >> 3, qc = gid & 7;
            int m = m0 + row;
            if (k0 < 256)
                areg[q] = *(const float4*)(heads + (size_t)m * 256 + k0 + qc * 4);
            else
                areg[q] = *(const float4*)(g_cell + (size_t)m * 256 + (k0 - 256) + qc * 4);
            breg[q] = *(const float4*)(W + (size_t)(n0 + row) * 512 + k0 + qc * 4);
        }
    };
    auto sts = [&](int buf) {
        #pragma unroll
        for (int q = 0; q < 4; q++) {
            int gid = t + q * 256, row = gid >> 3, qc = gid & 7;
            uint32_t* da = As + buf * 4096 + row * 32 + ((qc ^ (row & 7)) << 2);
            da[0] = f2tf(areg[q].x); da[1] = f2tf(areg[q].y);
            da[2] = f2tf(areg[q].z); da[3] = f2tf(areg[q].w);
            uint32_t* db = Bs + buf * 4096 + row * 32 + ((qc ^ (row & 7)) << 2);
            db[0] = f2tf(breg[q].x); db[1] = f2tf(breg[q].y);
            db[2] = f2tf(breg[q].z); db[3] = f2tf(breg[q].w);
        }
    };

    ldg(0); sts(0);
    __syncthreads();
    int cur = 0;

    for (int c = 0; c < 16; c++) {
        bool more = (c < 15);
        if (more) ldg(c + 1);
        const uint32_t* Ab = As + cur * 4096;
        const uint32_t* Bb = Bs + cur * 4096;
        #pragma unroll
        for (int ks = 0; ks < 4; ks++) {
            int c0 = (((2 * ks)     ^ g) << 2) + tg;
            int c1 = (((2 * ks + 1) ^ g) << 2) + tg;
            uint32_t af[4][4];
            #pragma unroll
            for (int fm = 0; fm < 4; fm++) {
                int base = (wm * 64 + fm * 16 + g) * 32;
                af[fm][0] = Ab[base + c0];
                af[fm][1] = Ab[base + 256 + c0];
                af[fm][2] = Ab[base + c1];
                af[fm][3] = Ab[base + 256 + c1];
            }
            #pragma unroll
            for (int fn = 0; fn < 4; fn++) {
                int nb = (wn * 32 + fn * 8 + g) * 32;
                uint32_t b0 = Bb[nb + c0], b1 = Bb[nb + c1];
                #pragma unroll
                for (int fm = 0; fm < 4; fm++)
                    MMA_TF32(acc[fm][fn], af[fm], b0, b1);
            }
        }
        if (more) {
            sts(cur ^ 1);
            __syncthreads();
            cur ^= 1;
        }
    }

    // stage D to smem
    __syncthreads();
    #pragma unroll
    for (int fm = 0; fm < 4; fm++) {
        int r0 = wm * 64 + fm * 16 + g;
        #pragma unroll
        for (int fn = 0; fn < 4; fn++) {
            int col = wn * 32 + fn * 8 + 2 * tg;
            *(float2*)&stage[r0 * 136 + col]       = make_float2(acc[fm][fn][0], acc[fm][fn][1]);
            *(float2*)&stage[(r0 + 8) * 136 + col] = make_float2(acc[fm][fn][2], acc[fm][fn][3]);
        }
    }
    __syncthreads();

    // epilogue
    int row = t >> 1, half = (t & 1) * 64;
    int m = m0 + row;
    const float* sr = stage + row * 136;
    #pragma unroll
    for (int j = 0; j < 64; j += 4) {
        int col = half + j;
        int od = n0 + col;
        float4 dv = *(const float4*)(sr + col);
        float4 bb = *(const float4*)(bias + od);
        float4 cl = *(const float4*)(g_cell + (size_t)m * 256 + od);
        float4 v;
        v.x = sigmoidf_(dv.x + bb.x) * cl.x;
        v.y = sigmoidf_(dv.y + bb.y) * cl.y;
        v.z = sigmoidf_(dv.z + bb.z) * cl.z;
        v.w = sigmoidf_(dv.w + bb.w) * cl.w;
        *(float4*)(out + (size_t)m * 256 + od) = v;
    }
}

// ---------------------------------------------------------------------------
// Scan: c <- f*c + igh over S (associative blocked scan)
// ---------------------------------------------------------------------------
__global__ void scan_kernel(const float* __restrict__ init_cx) {
    int lane = threadIdx.x;
    int r    = threadIdx.y;
    int idt  = blockIdx.x & 7;
    int h    = (blockIdx.x >> 3) & 7;
    int b    = blockIdx.x >> 6;
    int od   = idt * 32 + lane;
    size_t base = (size_t)b * Ssz * SSTRIDE + (size_t)h * 256 + od;
    const int CH = Ssz / 16;

    size_t p = base + (size_t)(r * CH) * SSTRIDE;
    float F = 1.f, I = 0.f;
    for (int i = 0; i < CH; i++) {
        float f = g_f[p], ig = g_cell[p];
        I = fmaf(f, I, ig);
        F *= f;
        p += SSTRIDE;
    }
    __shared__ float sF[16][32], sI[16][32];
    sF[r][lane] = F; sI[r][lane] = I;
    __syncthreads();
    if (r == 0) {
        float c = init_cx[h * 256 + od];
        #pragma unroll
        for (int k2 = 0; k2 < 16; k2++) {
            float nf = sF[k2][lane], ni = sI[k2][lane];
            sI[k2][lane] = c;
            c = fmaf(nf, c, ni);
        }
    }
    __syncthreads();
    float c = sI[r][lane];
    p = base + (size_t)(r * CH) * SSTRIDE;
    for (int i = 0; i < CH; i++) {
        float f = g_f[p], ig = g_cell[p];
        c = fmaf(f, c, ig);
        g_cell[p] = c;
        p += SSTRIDE;
    }
}

// ---------------------------------------------------------------------------
extern "C" void kernel_launch(void* const* d_in, const int* in_sizes, int n_in,
                              void* d_out, int out_size)
{
    const float* heads   = (const float*)d_in[0];
    const float* W_hid   = (const float*)d_in[1];
    const float* b_hid   = (const float*)d_in[2];
    const float* W_og    = (const float*)d_in[3];
    const float* b_og    = (const float*)d_in[4];
    const float* ln_w    = (const float*)d_in[5];
    const float* ln_b    = (const float*)d_in[6];
    const float* init_cx = (const float*)d_in[7];
    float* out = (float*)d_out;

    cudaFuncSetAttribute(gemm1_t, cudaFuncAttributeMaxDynamicSharedMemorySize, G1_SMEM);
    cudaFuncSetAttribute(gemm2_t, cudaFuncAttributeMaxDynamicSharedMemorySize, G2_SMEM);

    repack_kernel<<<768, 128>>>(W_hid);
    cumsum_kernel<<<512, dim3(32, 16)>>>(heads);
    stats_kernel<<<BSN, 256>>>();
    gemm1_t<<<dim3(4, Mrows / 128), 256, G1_SMEM>>>(heads, b_hid, ln_w, ln_b);
    scan_kernel<<<512, dim3(32, 16)>>>(init_cx);
    gemm2_t<<<dim3(2, Mrows / 128), 256, G2_SMEM>>>(heads, W_og, b_og, out);
}

// round 13
// speedup vs baseline: 2.7238x; 1.1532x over previous
#include <cuda_runtime.h>
#include <math.h>
#include <stdint.h>

// Problem constants
#define Bsz   8
#define Ssz   2048
#define Hsz   8
#define Mrows (Bsz*Ssz*Hsz)    // 131072 rows (b,s,h)
#define Ktot  512
#define BSN   (Bsz*Ssz)
#define SSTRIDE 2048

// Scratch
__device__ float g_csum  [(size_t)Mrows*256];   // csum -> LN-normalized tf32
__device__ float g_headstf[(size_t)Mrows*256];  // tf32-rounded heads
__device__ float g_f     [(size_t)Mrows*256];
__device__ float g_cell  [(size_t)Mrows*256];   // igh, then exact cell
__device__ float g_celltf[(size_t)Mrows*256];   // tf32-rounded cell
__device__ float g_Wp    [768*512];             // repacked+rounded W_hid
__device__ float g_Wog   [256*512];             // rounded W_og

__device__ __forceinline__ float sigmoidf_(float x) {
    return 1.0f / (1.0f + __expf(-x));
}
__device__ __forceinline__ float tfr(float x) {
    uint32_t u;
    asm("cvt.rna.tf32.f32 %0, %1;" : "=r"(u) : "f"(x));
    return __uint_as_float(u);
}
#define MMA_TF32(d, a, b0, b1) \
    asm volatile("mma.sync.aligned.m16n8k8.row.col.f32.tf32.tf32.f32 " \
        "{%0,%1,%2,%3}, {%4,%5,%6,%7}, {%8,%9}, {%0,%1,%2,%3};" \
        : "+f"(d[0]), "+f"(d[1]), "+f"(d[2]), "+f"(d[3]) \
        : "r"(a[0]), "r"(a[1]), "r"(a[2]), "r"(a[3]), "r"(b0), "r"(b1))

#define CPA(dst, src) asm volatile("cp.async.cg.shared.global [%0], [%1], 16;" :: "r"(dst), "l"(src) : "memory")
#define CPC()         asm volatile("cp.async.commit_group;" ::: "memory")
#define CPW2()        asm volatile("cp.async.wait_group 2;" ::: "memory")

__device__ __forceinline__ uint32_t s2u(const void* p) {
    uint32_t a;
    asm("{ .reg .u64 t; cvta.to.shared.u64 t, %1; cvt.u32.u64 %0, t; }"
        : "=r"(a) : "l"(p));
    return a;
}

// ---------------------------------------------------------------------------
// cumsum over S per (b,h,id); also emits tf32-rounded heads.
// ---------------------------------------------------------------------------
__global__ void cumsum_kernel(const float* __restrict__ x) {
    int lane = threadIdx.x;
    int r    = threadIdx.y;
    int idt  = blockIdx.x & 7;
    int h    = (blockIdx.x >> 3) & 7;
    int b    = blockIdx.x >> 6;
    int id   = idt * 32 + lane;
    size_t base = (size_t)b * Ssz * SSTRIDE + (size_t)h * 256 + id;
    const int CH = Ssz / 16;

    size_t p = base + (size_t)(r * CH) * SSTRIDE;
    float sum = 0.f;
    #pragma unroll 8
    for (int i = 0; i < CH; i++) { sum += x[p]; p += SSTRIDE; }

    __shared__ float cs[16][32];
    cs[r][lane] = sum;
    __syncthreads();
    if (r == 0) {
        float a = 0.f;
        #pragma unroll
        for (int k2 = 0; k2 < 16; k2++) { float v = cs[k2][lane]; cs[k2][lane] = a; a += v; }
    }
    __syncthreads();

    float run = cs[r][lane];
    p = base + (size_t)(r * CH) * SSTRIDE;
    #pragma unroll 8
    for (int i = 0; i < CH; i++) {
        float v = x[p];
        run += v;
        g_csum[p] = run;
        g_headstf[p] = tfr(v);
        p += SSTRIDE;
    }
}

// ---------------------------------------------------------------------------
// LayerNorm stats per (b,s) + in-place normalize (tf32-rounded) of g_csum.
// ---------------------------------------------------------------------------
__global__ void stats_kernel(const float* __restrict__ lnw,
                             const float* __restrict__ lnb) {
    int bs = blockIdx.x;
    float4* p = (float4*)(g_csum + (size_t)bs * 2048);
    float s = 0.f, ss = 0.f;
    for (int i = threadIdx.x; i < 512; i += 256) {
        float4 v = p[i];
        s  += v.x + v.y + v.z + v.w;
        ss += v.x*v.x + v.y*v.y + v.z*v.z + v.w*v.w;
    }
    #pragma unroll
    for (int o = 16; o; o >>= 1) {
        s  += __shfl_down_sync(0xffffffffu, s,  o);
        ss += __shfl_down_sync(0xffffffffu, ss, o);
    }
    __shared__ float ws[8], wss[8];
    __shared__ float smu, srs;
    int wid = threadIdx.x >> 5, lane = threadIdx.x & 31;
    if (lane == 0) { ws[wid] = s; wss[wid] = ss; }
    __syncthreads();
    if (threadIdx.x == 0) {
        float S1 = 0.f, S2 = 0.f;
        #pragma unroll
        for (int i = 0; i < 8; i++) { S1 += ws[i]; S2 += wss[i]; }
        float mean = S1 * (1.f / 2048.f);
        float var  = S2 * (1.f / 2048.f) - mean * mean;
        smu = mean;
        srs = rsqrtf(var + 1e-6f);
    }
    __syncthreads();
    float mu = smu, rs = srs;
    const float4* w4 = (const float4*)lnw;
    const float4* b4 = (const float4*)lnb;
    for (int i = threadIdx.x; i < 512; i += 256) {
        float4 v = p[i], w = w4[i], b = b4[i];
        v.x = tfr((v.x - mu) * rs * w.x + b.x);
        v.y = tfr((v.y - mu) * rs * w.y + b.y);
        v.z = tfr((v.z - mu) * rs * w.z + b.z);
        v.w = tfr((v.w - mu) * rs * w.w + b.w);
        p[i] = v;
    }
}

// ---------------------------------------------------------------------------
// Repack+round W_hid: Wp[ob*192 + gate*64 + odl] = W_hid[gate*256 + ob*64 + odl]
// ---------------------------------------------------------------------------
__global__ void repack_kernel(const float* __restrict__ W) {
    int r = blockIdx.x;               // 0..767
    int ob = r / 192, rem = r % 192;
    int gate = rem / 64, odl = rem % 64;
    int src = gate * 256 + ob * 64 + odl;
    const float4* s = (const float4*)(W + (size_t)src * 512);
    float4* d = (float4*)(g_Wp + (size_t)r * 512);
    float4 v = s[threadIdx.x];
    v.x = tfr(v.x); v.y = tfr(v.y); v.z = tfr(v.z); v.w = tfr(v.w);
    d[threadIdx.x] = v;
}
__global__ void repack_og(const float* __restrict__ W) {
    int r = blockIdx.x;               // 0..255
    const float4* s = (const float4*)(W + (size_t)r * 512);
    float4* d = (float4*)(g_Wog + (size_t)r * 512);
    float4 v = s[threadIdx.x];
    v.x = tfr(v.x); v.y = tfr(v.y); v.z = tfr(v.z); v.w = tfr(v.w);
    d[threadIdx.x] = v;
}

// ---------------------------------------------------------------------------
// GEMM1 (mma.sync tf32, cp.async 3-stage): CTA 128m x 192n = {i|f|h} x 64 od.
// ---------------------------------------------------------------------------
#define G1_STAGE 40960              // 16384 A + 24576 B
#define G1_SMEM  (3*G1_STAGE)       // 122880 >= 102400 epilogue stage
__global__ __launch_bounds__(256)
void gemm1_t(const float* __restrict__ bias)
{
    extern __shared__ char smem[];
    uint32_t sb = s2u(smem);

    int t = threadIdx.x, w = t >> 5, lane = t & 31;
    int g = lane >> 2, tg = lane & 3;
    int wm = w >> 2, wn = w & 3;
    int ob = blockIdx.x;                 // od block 0..3
    int m0 = blockIdx.y * 128;
    int nbase = ob * 192;

    const char* srcAh[4]; const char* srcAc[4]; uint32_t dstA[4];
    const char* srcB[6];  uint32_t dstB[6];
    #pragma unroll
    for (int q = 0; q < 4; q++) {
        int gid = t + q * 256, row = gid >> 3, qc = gid & 7;
        srcAh[q] = (const char*)(g_headstf + (size_t)(m0 + row) * 256 + qc * 4);
        srcAc[q] = (const char*)(g_csum    + (size_t)(m0 + row) * 256 + qc * 4);
        dstA[q]  = row * 128 + ((qc ^ (row & 7)) << 4);
    }
    #pragma unroll
    for (int q = 0; q < 6; q++) {
        int gid = t + q * 256, row = gid >> 3, qc = gid & 7;
        srcB[q] = (const char*)(g_Wp + (size_t)(nbase + row) * 512 + qc * 4);
        dstB[q] = row * 128 + ((qc ^ (row & 7)) << 4);
    }

    auto issue = [&](int c) {
        uint32_t base = sb + (c % 3) * G1_STAGE;
        int k0 = c * 32;
        if (k0 < 256) {
            #pragma unroll
            for (int q = 0; q < 4; q++) CPA(base + dstA[q], srcAh[q] + (size_t)k0 * 4);
        } else {
            #pragma unroll
            for (int q = 0; q < 4; q++) CPA(base + dstA[q], srcAc[q] + (size_t)(k0 - 256) * 4);
        }
        uint32_t bb = base + 16384;
        #pragma unroll
        for (int q = 0; q < 6; q++) CPA(bb + dstB[q], srcB[q] + (size_t)k0 * 4);
        CPC();
    };

    float acc[4][6][4];
    #pragma unroll
    for (int i = 0; i < 4; i++)
        #pragma unroll
        for (int j = 0; j < 6; j++)
            #pragma unroll
            for (int k = 0; k < 4; k++) acc[i][j][k] = 0.f;

    issue(0); issue(1); issue(2);

    for (int c = 0; c < 16; c++) {
        CPW2();
        __syncthreads();
        const uint32_t* Ab = (const uint32_t*)(smem + (c % 3) * G1_STAGE);
        const uint32_t* Bb = (const uint32_t*)(smem + (c % 3) * G1_STAGE + 16384);
        #pragma unroll
        for (int ks = 0; ks < 4; ks++) {
            int c0 = (((2 * ks)     ^ g) << 2) + tg;
            int c1 = (((2 * ks + 1) ^ g) << 2) + tg;
            uint32_t af[4][4];
            #pragma unroll
            for (int fm = 0; fm < 4; fm++) {
                int base = (wm * 64 + fm * 16 + g) * 32;
                af[fm][0] = Ab[base + c0];
                af[fm][1] = Ab[base + 256 + c0];
                af[fm][2] = Ab[base + c1];
                af[fm][3] = Ab[base + 256 + c1];
            }
            #pragma unroll
            for (int fn = 0; fn < 6; fn++) {
                int nb = (wn * 48 + fn * 8 + g) * 32;
                uint32_t b0 = Bb[nb + c0], b1 = Bb[nb + c1];
                #pragma unroll
                for (int fm = 0; fm < 4; fm++)
                    MMA_TF32(acc[fm][fn], af[fm], b0, b1);
            }
        }
        __syncthreads();
        // pipeline-tail fix: always commit exactly one group per iteration so
        // wait_group 2 at iteration c guarantees group c is complete.
        if (c + 3 < 16) issue(c + 3); else CPC();
    }

    // stage D to smem
    float* stage = (float*)smem;      // 128 x 200
    #pragma unroll
    for (int fm = 0; fm < 4; fm++) {
        int r0 = wm * 64 + fm * 16 + g;
        #pragma unroll
        for (int fn = 0; fn < 6; fn++) {
            int col = wn * 48 + fn * 8 + 2 * tg;
            *(float2*)&stage[r0 * 200 + col]       = make_float2(acc[fm][fn][0], acc[fm][fn][1]);
            *(float2*)&stage[(r0 + 8) * 200 + col] = make_float2(acc[fm][fn][2], acc[fm][fn][3]);
        }
    }
    __syncthreads();

    // epilogue: gates -> activations
    int row = t >> 1, half = (t & 1) * 32;
    int m = m0 + row;
    const float* sr = stage + row * 200;
    #pragma unroll
    for (int j = 0; j < 32; j += 4) {
        int odl = half + j;
        int od = ob * 64 + odl;
        float4 iv = *(const float4*)(sr + odl);
        float4 fv = *(const float4*)(sr + 64 + odl);
        float4 hv = *(const float4*)(sr + 128 + odl);
        float4 bi = *(const float4*)(bias + od);
        float4 bf = *(const float4*)(bias + 256 + od);
        float4 bh = *(const float4*)(bias + 512 + od);
        float4 fo, ig;
        fo.x = sigmoidf_(fv.x + bf.x);
        fo.y = sigmoidf_(fv.y + bf.y);
        fo.z = sigmoidf_(fv.z + bf.z);
        fo.w = sigmoidf_(fv.w + bf.w);
        ig.x = sigmoidf_(iv.x + bi.x) * fmaxf(hv.x + bh.x, 0.f);
        ig.y = sigmoidf_(iv.y + bi.y) * fmaxf(hv.y + bh.y, 0.f);
        ig.z = sigmoidf_(iv.z + bi.z) * fmaxf(hv.z + bh.z, 0.f);
        ig.w = sigmoidf_(iv.w + bi.w) * fmaxf(hv.w + bh.w, 0.f);
        *(float4*)(g_f    + (size_t)m * 256 + od) = fo;
        *(float4*)(g_cell + (size_t)m * 256 + od) = ig;
    }
}

// ---------------------------------------------------------------------------
// GEMM2 (mma.sync tf32, cp.async 3-stage): CTA 128m x 128n.
// ---------------------------------------------------------------------------
#define G2_STAGE 32768              // 16384 A + 16384 B
#define G2_SMEM  (3*G2_STAGE)       // 98304 >= 69632 epilogue stage
__global__ __launch_bounds__(256)
void gemm2_t(const float* __restrict__ bias, float* __restrict__ out)
{
    extern __shared__ char smem[];
    uint32_t sb = s2u(smem);

    int t = threadIdx.x, w = t >> 5, lane = t & 31;
    int g = lane >> 2, tg = lane & 3;
    int wm = w >> 2, wn = w & 3;
    int n0 = blockIdx.x * 128;
    int m0 = blockIdx.y * 128;

    const char* srcAh[4]; const char* srcAc[4]; const char* srcB[4];
    uint32_t dstQ[4];
    #pragma unroll
    for (int q = 0; q < 4; q++) {
        int gid = t + q * 256, row = gid >> 3, qc = gid & 7;
        srcAh[q] = (const char*)(g_headstf + (size_t)(m0 + row) * 256 + qc * 4);
        srcAc[q] = (const char*)(g_celltf  + (size_t)(m0 + row) * 256 + qc * 4);
        srcB[q]  = (const char*)(g_Wog + (size_t)(n0 + row) * 512 + qc * 4);
        dstQ[q]  = row * 128 + ((qc ^ (row & 7)) << 4);
    }

    auto issue = [&](int c) {
        uint32_t base = sb + (c % 3) * G2_STAGE;
        int k0 = c * 32;
        if (k0 < 256) {
            #pragma unroll
            for (int q = 0; q < 4; q++) CPA(base + dstQ[q], srcAh[q] + (size_t)k0 * 4);
        } else {
            #pragma unroll
            for (int q = 0; q < 4; q++) CPA(base + dstQ[q], srcAc[q] + (size_t)(k0 - 256) * 4);
        }
        uint32_t bb = base + 16384;
        #pragma unroll
        for (int q = 0; q < 4; q++) CPA(bb + dstQ[q], srcB[q] + (size_t)k0 * 4);
        CPC();
    };

    float acc[4][4][4];
    #pragma unroll
    for (int i = 0; i < 4; i++)
        #pragma unroll
        for (int j = 0; j < 4; j++)
            #pragma unroll
            for (int k = 0; k < 4; k++) acc[i][j][k] = 0.f;

    issue(0); issue(1); issue(2);

    for (int c = 0; c < 16; c++) {
        CPW2();
        __syncthreads();
        const uint32_t* Ab = (const uint32_t*)(smem + (c % 3) * G2_STAGE);
        const uint32_t* Bb = (const uint32_t*)(smem + (c % 3) * G2_STAGE + 16384);
        #pragma unroll
        for (int ks = 0; ks < 4; ks++) {
            int c0 = (((2 * ks)     ^ g) << 2) + tg;
            int c1 = (((2 * ks + 1) ^ g) << 2) + tg;
            uint32_t af[4][4];
            #pragma unroll
            for (int fm = 0; fm < 4; fm++) {
                int base = (wm * 64 + fm * 16 + g) * 32;
                af[fm][0] = Ab[base + c0];
                af[fm][1] = Ab[base + 256 + c0];
                af[fm][2] = Ab[base + c1];
                af[fm][3] = Ab[base + 256 + c1];
            }
            #pragma unroll
            for (int fn = 0; fn < 4; fn++) {
                int nb = (wn * 32 + fn * 8 + g) * 32;
                uint32_t b0 = Bb[nb + c0], b1 = Bb[nb + c1];
                #pragma unroll
                for (int fm = 0; fm < 4; fm++)
                    MMA_TF32(acc[fm][fn], af[fm], b0, b1);
            }
        }
        __syncthreads();
        // pipeline-tail fix (see gemm1_t)
        if (c + 3 < 16) issue(c + 3); else CPC();
    }

    // stage D to smem
    float* stage = (float*)smem;      // 128 x 136
    #pragma unroll
    for (int fm = 0; fm < 4; fm++) {
        int r0 = wm * 64 + fm * 16 + g;
        #pragma unroll
        for (int fn = 0; fn < 4; fn++) {
            int col = wn * 32 + fn * 8 + 2 * tg;
            *(float2*)&stage[r0 * 136 + col]       = make_float2(acc[fm][fn][0], acc[fm][fn][1]);
            *(float2*)&stage[(r0 + 8) * 136 + col] = make_float2(acc[fm][fn][2], acc[fm][fn][3]);
        }
    }
    __syncthreads();

    // epilogue
    int row = t >> 1, half = (t & 1) * 64;
    int m = m0 + row;
    const float* sr = stage + row * 136;
    #pragma unroll
    for (int j = 0; j < 64; j += 4) {
        int col = half + j;
        int od = n0 + col;
        float4 dv = *(const float4*)(sr + col);
        float4 bb = *(const float4*)(bias + od);
        float4 cl = *(const float4*)(g_cell + (size_t)m * 256 + od);
        float4 v;
        v.x = sigmoidf_(dv.x + bb.x) * cl.x;
        v.y = sigmoidf_(dv.y + bb.y) * cl.y;
        v.z = sigmoidf_(dv.z + bb.z) * cl.z;
        v.w = sigmoidf_(dv.w + bb.w) * cl.w;
        *(float4*)(out + (size_t)m * 256 + od) = v;
    }
}

// ---------------------------------------------------------------------------
// Scan: c <- f*c + igh over S; writes exact cell and tf32-rounded cell.
// ---------------------------------------------------------------------------
__global__ void scan_kernel(const float* __restrict__ init_cx) {
    int lane = threadIdx.x;
    int r    = threadIdx.y;
    int idt  = blockIdx.x & 7;
    int h    = (blockIdx.x >> 3) & 7;
    int b    = blockIdx.x >> 6;
    int od   = idt * 32 + lane;
    size_t base = (size_t)b * Ssz * SSTRIDE + (size_t)h * 256 + od;
    const int CH = Ssz / 16;

    size_t p = base + (size_t)(r * CH) * SSTRIDE;
    float F = 1.f, I = 0.f;
    #pragma unroll 8
    for (int i = 0; i < CH; i++) {
        float f = g_f[p], ig = g_cell[p];
        I = fmaf(f, I, ig);
        F *= f;
        p += SSTRIDE;
    }
    __shared__ float sF[16][32], sI[16][32];
    sF[r][lane] = F; sI[r][lane] = I;
    __syncthreads();
    if (r == 0) {
        float c = init_cx[h * 256 + od];
        #pragma unroll
        for (int k2 = 0; k2 < 16; k2++) {
            float nf = sF[k2][lane], ni = sI[k2][lane];
            sI[k2][lane] = c;
            c = fmaf(nf, c, ni);
        }
    }
    __syncthreads();
    float c = sI[r][lane];
    p = base + (size_t)(r * CH) * SSTRIDE;
    #pragma unroll 8
    for (int i = 0; i < CH; i++) {
        float f = g_f[p], ig = g_cell[p];
        c = fmaf(f, c, ig);
        g_cell[p] = c;
        g_celltf[p] = tfr(c);
        p += SSTRIDE;
    }
}

// ---------------------------------------------------------------------------
extern "C" void kernel_launch(void* const* d_in, const int* in_sizes, int n_in,
                              void* d_out, int out_size)
{
    const float* heads   = (const float*)d_in[0];
    const float* W_hid   = (const float*)d_in[1];
    const float* b_hid   = (const float*)d_in[2];
    const float* W_og    = (const float*)d_in[3];
    const float* b_og    = (const float*)d_in[4];
    const float* ln_w    = (const float*)d_in[5];
    const float* ln_b    = (const float*)d_in[6];
    const float* init_cx = (const float*)d_in[7];
    float* out = (float*)d_out;

    cudaFuncSetAttribute(gemm1_t, cudaFuncAttributeMaxDynamicSharedMemorySize, G1_SMEM);
    cudaFuncSetAttribute(gemm2_t, cudaFuncAttributeMaxDynamicSharedMemorySize, G2_SMEM);

    repack_kernel<<<768, 128>>>(W_hid);
    repack_og<<<256, 128>>>(W_og);
    cumsum_kernel<<<512, dim3(32, 16)>>>(heads);
    stats_kernel<<<BSN, 256>>>(ln_w, ln_b);
    gemm1_t<<<dim3(4, Mrows / 128), 256, G1_SMEM>>>(b_hid);
    scan_kernel<<<512, dim3(32, 16)>>>(init_cx);
    gemm2_t<<<dim3(2, Mrows / 128), 256, G2_SMEM>>>(b_og, out);
}